// round 5
// baseline (speedup 1.0000x reference)
#include <cuda_runtime.h>
#include <cuda_bf16.h>
#include <cstdint>

// Problem constants
#define BB 8
#define QQ 128
#define KK 512
#define DD 256
#define UU 256
#define TQ 4               // q rows per attention block
#define KC 32              // kp rows per double-buffered chunk

// Scratch for projections (static device arrays: no allocation)
__device__ float g_qp[BB * QQ * UU];   // 1 MB
__device__ float g_kp[BB * KK * UU];   // 4 MB

// single-MUFU tanh
__device__ __forceinline__ float tanh_approx(float x) {
    float y;
    asm("tanh.approx.f32 %0, %1;" : "=f"(y) : "f"(x));
    return y;
}

__device__ __forceinline__ void cp_async16(uint32_t smem, const void* g) {
    asm volatile("cp.async.cg.shared.global [%0], [%1], 16;\n" :: "r"(smem), "l"(g));
}
__device__ __forceinline__ void cp_commit() { asm volatile("cp.async.commit_group;\n"); }
template <int N>
__device__ __forceinline__ void cp_wait() { asm volatile("cp.async.wait_group %0;\n" :: "n"(N)); }

// ---------------------------------------------------------------------------
// Merged projection GEMM: rows [0,1024) = query@Wq -> g_qp,
//                         rows [1024,5120) = key@Wk -> g_kp.
// BM=64, BN=64, BK=16, 128 threads, 8x4 per-thread tile.
// ---------------------------------------------------------------------------
__global__ __launch_bounds__(128) void proj_gemm(const float* __restrict__ query,
                                                 const float* __restrict__ key,
                                                 const float* __restrict__ Wq,
                                                 const float* __restrict__ Wk) {
    __shared__ float As[16][68];
    __shared__ float Ws[16][64];

    const int tid = threadIdx.x;
    const int m0  = blockIdx.y * 64;
    const int n0  = blockIdx.x * 64;

    const float* A; const float* W; float* C;
    if (m0 < BB * QQ) { A = query + (size_t)m0 * DD;             W = Wq; C = g_qp + (size_t)m0 * UU; }
    else              { A = key   + (size_t)(m0 - BB * QQ) * DD; W = Wk; C = g_kp + (size_t)(m0 - BB * QQ) * UU; }

    const int ty = tid >> 4;
    const int tx = tid & 15;

    const int ar0 = tid >> 2;
    const int ac  = (tid & 3) * 4;
    const int wr0 = tid >> 4;
    const int wc  = (tid & 15) * 4;

    float acc[8][4];
#pragma unroll
    for (int i = 0; i < 8; i++)
#pragma unroll
        for (int j = 0; j < 4; j++) acc[i][j] = 0.0f;

    for (int k0 = 0; k0 < DD; k0 += 16) {
        float4 a0 = *(const float4*)&A[(ar0)      * DD + k0 + ac];
        float4 a1 = *(const float4*)&A[(ar0 + 32) * DD + k0 + ac];
        float4 w0 = *(const float4*)&W[(k0 + wr0)     * UU + n0 + wc];
        float4 w1 = *(const float4*)&W[(k0 + wr0 + 8) * UU + n0 + wc];
        __syncthreads();
        As[ac + 0][ar0] = a0.x; As[ac + 1][ar0] = a0.y;
        As[ac + 2][ar0] = a0.z; As[ac + 3][ar0] = a0.w;
        As[ac + 0][ar0 + 32] = a1.x; As[ac + 1][ar0 + 32] = a1.y;
        As[ac + 2][ar0 + 32] = a1.z; As[ac + 3][ar0 + 32] = a1.w;
        *(float4*)&Ws[wr0][wc]     = w0;
        *(float4*)&Ws[wr0 + 8][wc] = w1;
        __syncthreads();
#pragma unroll
        for (int kk = 0; kk < 16; kk++) {
            float4 av0 = *(const float4*)&As[kk][ty * 8];
            float4 av1 = *(const float4*)&As[kk][ty * 8 + 4];
            float4 wv  = *(const float4*)&Ws[kk][tx * 4];
            float am[8] = {av0.x, av0.y, av0.z, av0.w, av1.x, av1.y, av1.z, av1.w};
            float wn[4] = {wv.x, wv.y, wv.z, wv.w};
#pragma unroll
            for (int i = 0; i < 8; i++)
#pragma unroll
                for (int j = 0; j < 4; j++)
                    acc[i][j] = fmaf(am[i], wn[j], acc[i][j]);
        }
    }
#pragma unroll
    for (int i = 0; i < 8; i++) {
        float4 o = make_float4(acc[i][0], acc[i][1], acc[i][2], acc[i][3]);
        *(float4*)&C[(size_t)(ty * 8 + i) * UU + n0 + tx * 4] = o;
    }
}

// ---------------------------------------------------------------------------
// Attention: block = (b, q-tile of 4), batch-interleaved mapping. 256 thr.
// Warp w: q row (w&3), u-half (w>>2). Lane = k within 32-row chunk.
// 8 independent FMA chains per warp (2 x float4 accumulators over j / j+16).
// ---------------------------------------------------------------------------
#define SWZ(r, c) ((c) ^ ((r) & 7))

__global__ __launch_bounds__(256) void attn_kernel(const float* __restrict__ value,
                                                   const int* __restrict__ valid_len,
                                                   const float* __restrict__ v_w,
                                                   float* __restrict__ out) {
    extern __shared__ float smem[];
    float4* kb   = (float4*)smem;                 // [2][32][64] f4 (swizzled)  64KB
    float*  qp_s = smem + 2 * KC * UU;            //                             4KB
    float*  v_s  = qp_s + TQ * UU;                //                             1KB
    float*  sc   = v_s + UU;                      // [2][4][512] partials       16KB

    const int tid = threadIdx.x;
    const int b   = blockIdx.x & 7;               // batch-interleaved for balance
    const int q0  = (blockIdx.x >> 3) * TQ;
    const int vl  = __ldg(&valid_len[b]);
    const int w   = tid >> 5, l = tid & 31;
    const int r   = w & 3;         // q row within tile
    const int uh  = w >> 2;        // u half (0/1)

    // stage qp tile + v_w
    const float4* qg = (const float4*)(g_qp + (size_t)(b * QQ + q0) * UU);
    ((float4*)qp_s)[tid] = qg[tid];
    if (tid < 64) ((float4*)v_s)[tid] = ((const float4*)v_w)[tid];

    const float* kpg = g_kp + (size_t)b * KK * UU;
    const uint32_t kb_base = (uint32_t)__cvta_generic_to_shared(kb);

    const int nch = (vl + KC - 1) / KC;

    // prefetch chunk 0
    {
        const float4* src = (const float4*)kpg;
#pragma unroll
        for (int i = 0; i < 8; i++) {
            int idx = tid + i * 256;
            int rr = idx >> 6, cc = idx & 63;
            cp_async16(kb_base + ((uint32_t)(rr * 64 + SWZ(rr, cc)) << 4), src + idx);
        }
        cp_commit();
    }

    const float4* qrow4 = (const float4*)(qp_s + r * UU);
    const float4* vw4   = (const float4*)v_s;
    const int ubase = uh * 32;
    const int swl   = l & 7;

    for (int c = 0; c < nch; c++) {
        if (c + 1 < nch) {
            const float4* src = (const float4*)(kpg + (size_t)(c + 1) * KC * UU);
            const uint32_t bufo = (uint32_t)(((c + 1) & 1) * 2048) << 4;
#pragma unroll
            for (int i = 0; i < 8; i++) {
                int idx = tid + i * 256;
                int rr = idx >> 6, cc = idx & 63;
                cp_async16(kb_base + bufo + ((uint32_t)(rr * 64 + SWZ(rr, cc)) << 4), src + idx);
            }
            cp_commit();
            cp_wait<1>();
        } else {
            cp_wait<0>();
        }
        __syncthreads();

        const float4* kbuf = kb + (c & 1) * 2048 + l * 64;
        float4 aA = make_float4(0.f, 0.f, 0.f, 0.f);   // chains for j
        float4 aB = make_float4(0.f, 0.f, 0.f, 0.f);   // chains for j+16
#pragma unroll
        for (int j = 0; j < 16; j++) {
            int ua = ubase + j, ub = ubase + j + 16;
            float4 qa = qrow4[ua], va = vw4[ua], ka = kbuf[ua ^ swl];
            float4 qb = qrow4[ub], vb = vw4[ub], kc4 = kbuf[ub ^ swl];
            aA.x = fmaf(va.x, tanh_approx(qa.x + ka.x), aA.x);
            aA.y = fmaf(va.y, tanh_approx(qa.y + ka.y), aA.y);
            aA.z = fmaf(va.z, tanh_approx(qa.z + ka.z), aA.z);
            aA.w = fmaf(va.w, tanh_approx(qa.w + ka.w), aA.w);
            aB.x = fmaf(vb.x, tanh_approx(qb.x + kc4.x), aB.x);
            aB.y = fmaf(vb.y, tanh_approx(qb.y + kc4.y), aB.y);
            aB.z = fmaf(vb.z, tanh_approx(qb.z + kc4.z), aB.z);
            aB.w = fmaf(vb.w, tanh_approx(qb.w + kc4.w), aB.w);
        }
        float acc = ((aA.x + aA.y) + (aA.z + aA.w)) + ((aB.x + aB.y) + (aB.z + aB.w));
        sc[(uh * TQ + r) * KK + c * KC + l] = acc;
        __syncthreads();
    }

    // ---- masked softmax: warps 0..3, warp w owns row w ----
    if (w < 4) {
        float* rowA = sc + w * KK;
        float* rowB = sc + (TQ + w) * KK;
        float vals[16];
        float m = -3.0e38f;
#pragma unroll
        for (int i = 0; i < 16; i++) {
            int k = l + 32 * i;
            float s = (k < vl) ? (rowA[k] + rowB[k]) : -1e6f;
            vals[i] = s;
            m = fmaxf(m, s);
        }
#pragma unroll
        for (int off = 16; off; off >>= 1) m = fmaxf(m, __shfl_xor_sync(0xffffffffu, m, off));
        float ssum = 0.0f;
#pragma unroll
        for (int i = 0; i < 16; i++) {
            float e = __expf(vals[i] - m);
            vals[i] = e;
            ssum += e;
        }
#pragma unroll
        for (int off = 16; off; off >>= 1) ssum += __shfl_xor_sync(0xffffffffu, ssum, off);
        float inv = 1.0f / ssum;
#pragma unroll
        for (int i = 0; i < 16; i++) rowA[l + 32 * i] = vals[i] * inv;
    }
    __syncthreads();

    // ---- output: thread tid = feature d; skip k >= valid_len (attn == 0) ----
    float oacc[TQ];
#pragma unroll
    for (int q = 0; q < TQ; q++) oacc[q] = 0.0f;
    const float* vb = value + (size_t)b * KK * DD;
    const int kend = (vl + 3) & ~3;
#pragma unroll 2
    for (int k = 0; k < kend; k += 4) {
        float v0 = vb[(k + 0) * DD + tid];
        float v1 = vb[(k + 1) * DD + tid];
        float v2 = vb[(k + 2) * DD + tid];
        float v3 = vb[(k + 3) * DD + tid];
#pragma unroll
        for (int q = 0; q < TQ; q++) {
            float4 a = *(const float4*)&sc[q * KK + k];
            oacc[q] = fmaf(a.x, v0, fmaf(a.y, v1, fmaf(a.z, v2, fmaf(a.w, v3, oacc[q]))));
        }
    }
    float* ob = out + (size_t)(b * QQ + q0) * DD;
#pragma unroll
    for (int q = 0; q < TQ; q++) ob[q * DD + tid] = oacc[q];
}

// ---------------------------------------------------------------------------
// Launch
// ---------------------------------------------------------------------------
extern "C" void kernel_launch(void* const* d_in, const int* in_sizes, int n_in,
                              void* d_out, int out_size) {
    const float* query     = (const float*)d_in[0];
    const float* key       = (const float*)d_in[1];
    const float* value     = (const float*)d_in[2];
    const int*   valid_len = (const int*)d_in[3];
    const float* Wq        = (const float*)d_in[4];
    const float* Wk        = (const float*)d_in[5];
    const float* v_w       = (const float*)d_in[6];
    float* out = (float*)d_out;

    proj_gemm<<<dim3(UU / 64, (BB * QQ + BB * KK) / 64), 128>>>(query, key, Wq, Wk);

    const int smem_attn = (2 * KC * UU + TQ * UU + UU + 2 * TQ * KK) * (int)sizeof(float); // 87KB
    cudaFuncSetAttribute(attn_kernel, cudaFuncAttributeMaxDynamicSharedMemorySize, smem_attn);
    attn_kernel<<<BB * (QQ / TQ), 256, smem_attn>>>(value, valid_len, v_w, out);
}

// round 6
// speedup vs baseline: 1.1440x; 1.1440x over previous
#include <cuda_runtime.h>
#include <cuda_bf16.h>
#include <cstdint>

// Problem constants
#define BB 8
#define QQ 128
#define KK 512
#define DD 256
#define UU 256
#define TQ 4               // q rows per tile
#define KC 32              // k rows per score block

// Scratch (static device arrays: no allocation)
__device__ float g_qp[BB * QQ * UU];   // 1 MB
__device__ float g_kp[BB * KK * UU];   // 4 MB
__device__ float g_sc[BB * QQ * KK];   // 2 MB raw scores

// single-MUFU tanh
__device__ __forceinline__ float tanh_approx(float x) {
    float y;
    asm("tanh.approx.f32 %0, %1;" : "=f"(y) : "f"(x));
    return y;
}

__device__ __forceinline__ void cp_async16(uint32_t smem, const void* g) {
    asm volatile("cp.async.cg.shared.global [%0], [%1], 16;\n" :: "r"(smem), "l"(g));
}
__device__ __forceinline__ void cp_commit() { asm volatile("cp.async.commit_group;\n"); }
template <int N>
__device__ __forceinline__ void cp_wait() { asm volatile("cp.async.wait_group %0;\n" :: "n"(N)); }

// ---------------------------------------------------------------------------
// Merged projection GEMM: rows [0,1024) = query@Wq -> g_qp,
//                         rows [1024,5120) = key@Wk -> g_kp.
// BM=64, BN=64, BK=16, 128 threads, 8x4 per-thread tile. (~FFMA floor)
// ---------------------------------------------------------------------------
__global__ __launch_bounds__(128) void proj_gemm(const float* __restrict__ query,
                                                 const float* __restrict__ key,
                                                 const float* __restrict__ Wq,
                                                 const float* __restrict__ Wk) {
    __shared__ float As[16][68];
    __shared__ float Ws[16][64];

    const int tid = threadIdx.x;
    const int m0  = blockIdx.y * 64;
    const int n0  = blockIdx.x * 64;

    const float* A; const float* W; float* C;
    if (m0 < BB * QQ) { A = query + (size_t)m0 * DD;             W = Wq; C = g_qp + (size_t)m0 * UU; }
    else              { A = key   + (size_t)(m0 - BB * QQ) * DD; W = Wk; C = g_kp + (size_t)(m0 - BB * QQ) * UU; }

    const int ty = tid >> 4;
    const int tx = tid & 15;
    const int ar0 = tid >> 2;
    const int ac  = (tid & 3) * 4;
    const int wr0 = tid >> 4;
    const int wc  = (tid & 15) * 4;

    float acc[8][4];
#pragma unroll
    for (int i = 0; i < 8; i++)
#pragma unroll
        for (int j = 0; j < 4; j++) acc[i][j] = 0.0f;

    for (int k0 = 0; k0 < DD; k0 += 16) {
        float4 a0 = *(const float4*)&A[(ar0)      * DD + k0 + ac];
        float4 a1 = *(const float4*)&A[(ar0 + 32) * DD + k0 + ac];
        float4 w0 = *(const float4*)&W[(k0 + wr0)     * UU + n0 + wc];
        float4 w1 = *(const float4*)&W[(k0 + wr0 + 8) * UU + n0 + wc];
        __syncthreads();
        As[ac + 0][ar0] = a0.x; As[ac + 1][ar0] = a0.y;
        As[ac + 2][ar0] = a0.z; As[ac + 3][ar0] = a0.w;
        As[ac + 0][ar0 + 32] = a1.x; As[ac + 1][ar0 + 32] = a1.y;
        As[ac + 2][ar0 + 32] = a1.z; As[ac + 3][ar0 + 32] = a1.w;
        *(float4*)&Ws[wr0][wc]     = w0;
        *(float4*)&Ws[wr0 + 8][wc] = w1;
        __syncthreads();
#pragma unroll
        for (int kk = 0; kk < 16; kk++) {
            float4 av0 = *(const float4*)&As[kk][ty * 8];
            float4 av1 = *(const float4*)&As[kk][ty * 8 + 4];
            float4 wv  = *(const float4*)&Ws[kk][tx * 4];
            float am[8] = {av0.x, av0.y, av0.z, av0.w, av1.x, av1.y, av1.z, av1.w};
            float wn[4] = {wv.x, wv.y, wv.z, wv.w};
#pragma unroll
            for (int i = 0; i < 8; i++)
#pragma unroll
                for (int j = 0; j < 4; j++)
                    acc[i][j] = fmaf(am[i], wn[j], acc[i][j]);
        }
    }
#pragma unroll
    for (int i = 0; i < 8; i++) {
        float4 o = make_float4(acc[i][0], acc[i][1], acc[i][2], acc[i][3]);
        *(float4*)&C[(size_t)(ty * 8 + i) * UU + n0 + tx * 4] = o;
    }
}

// ---------------------------------------------------------------------------
// Score kernel: one block per (chunk, qtile, b). Uniform work, early-exit
// for chunks beyond valid_len. 256 thr: warp = (q row 0-3) x (u half 0-1).
// ---------------------------------------------------------------------------
__global__ __launch_bounds__(256, 4) void score_kernel(const int* __restrict__ valid_len,
                                                       const float* __restrict__ v_w) {
    __shared__ float4 kb[KC * 64];        // 32KB, swizzled chunk
    __shared__ float  qp_s[TQ * UU];      // 4KB
    __shared__ float  vw_s[UU];           // 1KB
    __shared__ float  part[TQ][32];       // u-half partials

    const int b  = blockIdx.z;
    const int vl = __ldg(&valid_len[b]);
    const int k0 = blockIdx.x * KC;
    if (k0 >= vl) return;                 // uniform block-wide exit

    const int tid = threadIdx.x;
    const int w = tid >> 5, l = tid & 31;
    const int r = w & 3, uh = w >> 2;
    const int q0 = blockIdx.y * TQ;

    // stage qp tile + v_w + kp chunk
    ((float4*)qp_s)[tid] = ((const float4*)(g_qp + (size_t)(b * QQ + q0) * UU))[tid];
    if (tid < 64) ((float4*)vw_s)[tid] = ((const float4*)v_w)[tid];

    const float4* src = (const float4*)(g_kp + ((size_t)b * KK + k0) * UU);
    const uint32_t kb_base = (uint32_t)__cvta_generic_to_shared(kb);
#pragma unroll
    for (int i = 0; i < 8; i++) {
        int idx = tid + i * 256;
        int rr = idx >> 6, cc = idx & 63;
        cp_async16(kb_base + ((uint32_t)(rr * 64 + (cc ^ (rr & 7))) << 4), src + idx);
    }
    cp_commit();
    cp_wait<0>();
    __syncthreads();

    const float4* qrow4 = (const float4*)(qp_s + r * UU);
    const float4* vw4   = (const float4*)vw_s;
    const float4* kbuf  = kb + l * 64;
    const int ubase = uh * 32;
    const int swl   = l & 7;

    float4 aA = make_float4(0.f, 0.f, 0.f, 0.f);
    float4 aB = make_float4(0.f, 0.f, 0.f, 0.f);
#pragma unroll
    for (int j = 0; j < 16; j++) {
        int ua = ubase + j, ub = ubase + j + 16;
        float4 qa = qrow4[ua], va = vw4[ua], ka  = kbuf[ua ^ swl];
        float4 qb = qrow4[ub], vb = vw4[ub], kc4 = kbuf[ub ^ swl];
        aA.x = fmaf(va.x, tanh_approx(qa.x + ka.x), aA.x);
        aA.y = fmaf(va.y, tanh_approx(qa.y + ka.y), aA.y);
        aA.z = fmaf(va.z, tanh_approx(qa.z + ka.z), aA.z);
        aA.w = fmaf(va.w, tanh_approx(qa.w + ka.w), aA.w);
        aB.x = fmaf(vb.x, tanh_approx(qb.x + kc4.x), aB.x);
        aB.y = fmaf(vb.y, tanh_approx(qb.y + kc4.y), aB.y);
        aB.z = fmaf(vb.z, tanh_approx(qb.z + kc4.z), aB.z);
        aB.w = fmaf(vb.w, tanh_approx(qb.w + kc4.w), aB.w);
    }
    float acc = ((aA.x + aA.y) + (aA.z + aA.w)) + ((aB.x + aB.y) + (aB.z + aB.w));

    if (uh) part[r][l] = acc;
    __syncthreads();
    if (!uh)
        g_sc[(size_t)(b * QQ + q0 + r) * KK + k0 + l] = acc + part[r][l];
}

// ---------------------------------------------------------------------------
// Softmax + output: block = (qtile, b), 256 threads.
// ---------------------------------------------------------------------------
__global__ __launch_bounds__(256) void softout_kernel(const float* __restrict__ value,
                                                      const int* __restrict__ valid_len,
                                                      float* __restrict__ out) {
    __shared__ float sc[TQ * KK];          // 8KB normalized attn

    const int tid = threadIdx.x;
    const int b   = blockIdx.y;
    const int q0  = blockIdx.x * TQ;
    const int vl  = __ldg(&valid_len[b]);
    const int w = tid >> 5, l = tid & 31;

    if (w < 4) {
        const float* row = g_sc + (size_t)(b * QQ + q0 + w) * KK;
        float vals[16];
        float m = -3.0e38f;
#pragma unroll
        for (int i = 0; i < 16; i++) {
            int k = l + 32 * i;
            float s = (k < vl) ? __ldg(&row[k]) : -1e6f;
            vals[i] = s;
            m = fmaxf(m, s);
        }
#pragma unroll
        for (int off = 16; off; off >>= 1) m = fmaxf(m, __shfl_xor_sync(0xffffffffu, m, off));
        float ssum = 0.0f;
#pragma unroll
        for (int i = 0; i < 16; i++) {
            float e = __expf(vals[i] - m);
            vals[i] = e;
            ssum += e;
        }
#pragma unroll
        for (int off = 16; off; off >>= 1) ssum += __shfl_xor_sync(0xffffffffu, ssum, off);
        float inv = 1.0f / ssum;
#pragma unroll
        for (int i = 0; i < 16; i++) sc[w * KK + l + 32 * i] = vals[i] * inv;
    }
    __syncthreads();

    // out = attn @ value ; thread tid = feature d, skip k >= valid_len
    float oacc[TQ];
#pragma unroll
    for (int q = 0; q < TQ; q++) oacc[q] = 0.0f;
    const float* vb = value + (size_t)b * KK * DD;
    const int kend = (vl + 3) & ~3;
#pragma unroll 2
    for (int k = 0; k < kend; k += 4) {
        float v0 = vb[(k + 0) * DD + tid];
        float v1 = vb[(k + 1) * DD + tid];
        float v2 = vb[(k + 2) * DD + tid];
        float v3 = vb[(k + 3) * DD + tid];
#pragma unroll
        for (int q = 0; q < TQ; q++) {
            float4 a = *(const float4*)&sc[q * KK + k];
            oacc[q] = fmaf(a.x, v0, fmaf(a.y, v1, fmaf(a.z, v2, fmaf(a.w, v3, oacc[q]))));
        }
    }
    float* ob = out + (size_t)(b * QQ + q0) * DD;
#pragma unroll
    for (int q = 0; q < TQ; q++) ob[q * DD + tid] = oacc[q];
}

// ---------------------------------------------------------------------------
// Launch
// ---------------------------------------------------------------------------
extern "C" void kernel_launch(void* const* d_in, const int* in_sizes, int n_in,
                              void* d_out, int out_size) {
    const float* query     = (const float*)d_in[0];
    const float* key       = (const float*)d_in[1];
    const float* value     = (const float*)d_in[2];
    const int*   valid_len = (const int*)d_in[3];
    const float* Wq        = (const float*)d_in[4];
    const float* Wk        = (const float*)d_in[5];
    const float* v_w       = (const float*)d_in[6];
    float* out = (float*)d_out;

    proj_gemm<<<dim3(UU / 64, (BB * QQ + BB * KK) / 64), 128>>>(query, key, Wq, Wk);
    score_kernel<<<dim3(KK / KC, QQ / TQ, BB), 256>>>(valid_len, v_w);
    softout_kernel<<<dim3(QQ / TQ, BB), 256>>>(value, valid_len, out);
}

// round 8
// speedup vs baseline: 1.1923x; 1.0423x over previous
#include <cuda_runtime.h>
#include <cuda_bf16.h>
#include <cstdint>

// Problem constants
#define BB 8
#define QQ 128
#define KK 512
#define DD 256
#define UU 256
#define TQ 4               // q rows per score block
#define KC 32              // k rows per score block
#define TQO 4              // q rows per softout block

// Scratch (static device arrays: no allocation)
__device__ float g_qp[BB * QQ * UU];   // 1 MB
__device__ float g_kp[BB * KK * UU];   // 4 MB
__device__ float g_sc[BB * QQ * KK];   // 2 MB raw scores

__device__ __forceinline__ float tanh_approx(float x) {
    float y;
    asm("tanh.approx.f32 %0, %1;" : "=f"(y) : "f"(x));
    return y;
}

__device__ __forceinline__ void cp_async16(uint32_t smem, const void* g) {
    asm volatile("cp.async.cg.shared.global [%0], [%1], 16;\n" :: "r"(smem), "l"(g));
}
__device__ __forceinline__ void cp_commit() { asm volatile("cp.async.commit_group;\n"); }
template <int N>
__device__ __forceinline__ void cp_wait() { asm volatile("cp.async.wait_group %0;\n" :: "n"(N)); }

// ---------------------------------------------------------------------------
// Merged projection GEMM with software-pipelined global loads.
// rows [0,1024) = query@Wq -> g_qp ; rows [1024,5120) = key@Wk -> g_kp.
// BM=64, BN=64, BK=16, 128 threads, 8x4 per-thread tile.
// ---------------------------------------------------------------------------
__global__ __launch_bounds__(128) void proj_gemm(const float* __restrict__ query,
                                                 const float* __restrict__ key,
                                                 const float* __restrict__ Wq,
                                                 const float* __restrict__ Wk) {
    __shared__ float As[16][68];
    __shared__ float Ws[16][64];

    const int tid = threadIdx.x;
    const int m0  = blockIdx.y * 64;
    const int n0  = blockIdx.x * 64;

    const float* A; const float* W; float* C;
    if (m0 < BB * QQ) { A = query + (size_t)m0 * DD;             W = Wq; C = g_qp + (size_t)m0 * UU; }
    else              { A = key   + (size_t)(m0 - BB * QQ) * DD; W = Wk; C = g_kp + (size_t)(m0 - BB * QQ) * UU; }

    const int ty = tid >> 4;
    const int tx = tid & 15;
    const int ar0 = tid >> 2;
    const int ac  = (tid & 3) * 4;
    const int wr0 = tid >> 4;
    const int wc  = (tid & 15) * 4;

    float acc[8][4];
#pragma unroll
    for (int i = 0; i < 8; i++)
#pragma unroll
        for (int j = 0; j < 4; j++) acc[i][j] = 0.0f;

    // preload slab 0
    float4 a0 = *(const float4*)&A[(ar0)      * DD + ac];
    float4 a1 = *(const float4*)&A[(ar0 + 32) * DD + ac];
    float4 w0 = *(const float4*)&W[(wr0)     * UU + n0 + wc];
    float4 w1 = *(const float4*)&W[(wr0 + 8) * UU + n0 + wc];

    for (int k0 = 0; k0 < DD; k0 += 16) {
        __syncthreads();
        As[ac + 0][ar0] = a0.x; As[ac + 1][ar0] = a0.y;
        As[ac + 2][ar0] = a0.z; As[ac + 3][ar0] = a0.w;
        As[ac + 0][ar0 + 32] = a1.x; As[ac + 1][ar0 + 32] = a1.y;
        As[ac + 2][ar0 + 32] = a1.z; As[ac + 3][ar0 + 32] = a1.w;
        *(float4*)&Ws[wr0][wc]     = w0;
        *(float4*)&Ws[wr0 + 8][wc] = w1;
        __syncthreads();
        if (k0 + 16 < DD) {   // issue next slab's loads; latency hides under compute
            a0 = *(const float4*)&A[(ar0)      * DD + k0 + 16 + ac];
            a1 = *(const float4*)&A[(ar0 + 32) * DD + k0 + 16 + ac];
            w0 = *(const float4*)&W[(k0 + 16 + wr0)     * UU + n0 + wc];
            w1 = *(const float4*)&W[(k0 + 16 + wr0 + 8) * UU + n0 + wc];
        }
#pragma unroll
        for (int kk = 0; kk < 16; kk++) {
            float4 av0 = *(const float4*)&As[kk][ty * 8];
            float4 av1 = *(const float4*)&As[kk][ty * 8 + 4];
            float4 wv  = *(const float4*)&Ws[kk][tx * 4];
            float am[8] = {av0.x, av0.y, av0.z, av0.w, av1.x, av1.y, av1.z, av1.w};
            float wn[4] = {wv.x, wv.y, wv.z, wv.w};
#pragma unroll
            for (int i = 0; i < 8; i++)
#pragma unroll
                for (int j = 0; j < 4; j++)
                    acc[i][j] = fmaf(am[i], wn[j], acc[i][j]);
        }
    }
#pragma unroll
    for (int i = 0; i < 8; i++) {
        float4 o = make_float4(acc[i][0], acc[i][1], acc[i][2], acc[i][3]);
        *(float4*)&C[(size_t)(ty * 8 + i) * UU + n0 + tx * 4] = o;
    }
}

// ---------------------------------------------------------------------------
// Score kernel v2: block per (chunk, qtile, b). 256 thr, 8 warps.
// Warp w owns u4-range [8w, 8w+8); lane l = k-row. q/vw loads are
// warp-uniform broadcasts (cheap); k loaded once per warp. MUFU-bound.
// ---------------------------------------------------------------------------
__global__ __launch_bounds__(256, 4) void score_kernel(const int* __restrict__ valid_len,
                                                       const float* __restrict__ v_w) {
    __shared__ float4 kb[KC * 64];        // 32KB swizzled kp chunk
    __shared__ float  qp_s[TQ * UU];      // 4KB
    __shared__ float  vw_s[UU];           // 1KB
    __shared__ float  part[8][TQ][32];    // 4KB u-partials

    const int b  = blockIdx.z;
    const int vl = __ldg(&valid_len[b]);
    const int k0 = blockIdx.x * KC;
    if (k0 >= vl) return;

    const int tid = threadIdx.x;
    const int q0  = blockIdx.y * TQ;

    ((float4*)qp_s)[tid] = ((const float4*)(g_qp + (size_t)(b * QQ + q0) * UU))[tid];
    if (tid < 64) ((float4*)vw_s)[tid] = ((const float4*)v_w)[tid];

    const float4* src = (const float4*)(g_kp + ((size_t)b * KK + k0) * UU);
    const uint32_t kb_base = (uint32_t)__cvta_generic_to_shared(kb);
#pragma unroll
    for (int i = 0; i < 8; i++) {
        int idx = tid + i * 256;
        int rr = idx >> 6, cc = idx & 63;
        cp_async16(kb_base + ((uint32_t)(rr * 64 + (cc ^ (rr & 7))) << 4), src + idx);
    }
    cp_commit();
    cp_wait<0>();
    __syncthreads();

    const int w = tid >> 5, l = tid & 31;
    const float4* kbuf = kb + l * 64;
    const float4* qp4  = (const float4*)qp_s;
    const float4* vw4  = (const float4*)vw_s;
    const int u0  = w * 8;
    const int swl = l & 7;

    float acc0 = 0.f, acc1 = 0.f, acc2 = 0.f, acc3 = 0.f;
#pragma unroll
    for (int j = 0; j < 8; j++) {
        const int u4 = u0 + j;
        float4 k4 = kbuf[u4 ^ swl];        // spread, conflict-free
        float4 vv = vw4[u4];               // uniform broadcast
        float4 q;
        q = qp4[0 * 64 + u4];              // uniform broadcast
        acc0 = fmaf(vv.x, tanh_approx(q.x + k4.x),
               fmaf(vv.y, tanh_approx(q.y + k4.y),
               fmaf(vv.z, tanh_approx(q.z + k4.z),
               fmaf(vv.w, tanh_approx(q.w + k4.w), acc0))));
        q = qp4[1 * 64 + u4];
        acc1 = fmaf(vv.x, tanh_approx(q.x + k4.x),
               fmaf(vv.y, tanh_approx(q.y + k4.y),
               fmaf(vv.z, tanh_approx(q.z + k4.z),
               fmaf(vv.w, tanh_approx(q.w + k4.w), acc1))));
        q = qp4[2 * 64 + u4];
        acc2 = fmaf(vv.x, tanh_approx(q.x + k4.x),
               fmaf(vv.y, tanh_approx(q.y + k4.y),
               fmaf(vv.z, tanh_approx(q.z + k4.z),
               fmaf(vv.w, tanh_approx(q.w + k4.w), acc2))));
        q = qp4[3 * 64 + u4];
        acc3 = fmaf(vv.x, tanh_approx(q.x + k4.x),
               fmaf(vv.y, tanh_approx(q.y + k4.y),
               fmaf(vv.z, tanh_approx(q.z + k4.z),
               fmaf(vv.w, tanh_approx(q.w + k4.w), acc3))));
    }
    part[w][0][l] = acc0;
    part[w][1][l] = acc1;
    part[w][2][l] = acc2;
    part[w][3][l] = acc3;
    __syncthreads();

    if (tid < TQ * 32) {
        const int r = tid >> 5, ll = tid & 31;
        float s = 0.f;
#pragma unroll
        for (int ww = 0; ww < 8; ww++) s += part[ww][r][ll];
        g_sc[(size_t)(b * QQ + q0 + r) * KK + k0 + ll] = s;
    }
}

// ---------------------------------------------------------------------------
// Softmax + output, d-split: block = (qtile, b, d-half). 128 threads.
// ---------------------------------------------------------------------------
__global__ __launch_bounds__(128) void softout_kernel(const float* __restrict__ value,
                                                      const int* __restrict__ valid_len,
                                                      float* __restrict__ out) {
    __shared__ float sc[TQO * KK];         // 8KB normalized attn

    const int tid = threadIdx.x;
    const int b   = blockIdx.y;
    const int q0  = blockIdx.x * TQO;
    const int dh  = blockIdx.z * 128;
    const int vl  = __ldg(&valid_len[b]);
    const int w = tid >> 5, l = tid & 31;

    {   // warp w handles softmax of row w (4 warps = 4 rows)
        const float* row = g_sc + (size_t)(b * QQ + q0 + w) * KK;
        float vals[16];
        float m = -3.0e38f;
#pragma unroll
        for (int i = 0; i < 16; i++) {
            int k = l + 32 * i;
            float s = (k < vl) ? __ldg(&row[k]) : -1e6f;
            vals[i] = s;
            m = fmaxf(m, s);
        }
#pragma unroll
        for (int off = 16; off; off >>= 1) m = fmaxf(m, __shfl_xor_sync(0xffffffffu, m, off));
        float ssum = 0.0f;
#pragma unroll
        for (int i = 0; i < 16; i++) {
            float e = __expf(vals[i] - m);
            vals[i] = e;
            ssum += e;
        }
#pragma unroll
        for (int off = 16; off; off >>= 1) ssum += __shfl_xor_sync(0xffffffffu, ssum, off);
        float inv = 1.0f / ssum;
#pragma unroll
        for (int i = 0; i < 16; i++) sc[w * KK + l + 32 * i] = vals[i] * inv;
    }
    __syncthreads();

    // out = attn @ value ; thread = feature (dh + tid)
    const int d = dh + tid;
    float oacc[TQO];
#pragma unroll
    for (int q = 0; q < TQO; q++) oacc[q] = 0.0f;
    const float* vb = value + (size_t)b * KK * DD;
    const int kend = (vl + 3) & ~3;
#pragma unroll 2
    for (int k = 0; k < kend; k += 4) {
        float v0 = vb[(k + 0) * DD + d];
        float v1 = vb[(k + 1) * DD + d];
        float v2 = vb[(k + 2) * DD + d];
        float v3 = vb[(k + 3) * DD + d];
#pragma unroll
        for (int q = 0; q < TQO; q++) {
            float4 a = *(const float4*)&sc[q * KK + k];
            oacc[q] = fmaf(a.x, v0, fmaf(a.y, v1, fmaf(a.z, v2, fmaf(a.w, v3, oacc[q]))));
        }
    }
    float* ob = out + (size_t)(b * QQ + q0) * DD + d;
#pragma unroll
    for (int q = 0; q < TQO; q++) ob[q * DD] = oacc[q];
}

// ---------------------------------------------------------------------------
// Launch
// ---------------------------------------------------------------------------
extern "C" void kernel_launch(void* const* d_in, const int* in_sizes, int n_in,
                              void* d_out, int out_size) {
    const float* query     = (const float*)d_in[0];
    const float* key       = (const float*)d_in[1];
    const float* value     = (const float*)d_in[2];
    const int*   valid_len = (const int*)d_in[3];
    const float* Wq        = (const float*)d_in[4];
    const float* Wk        = (const float*)d_in[5];
    const float* v_w       = (const float*)d_in[6];
    float* out = (float*)d_out;

    proj_gemm<<<dim3(UU / 64, (BB * QQ + BB * KK) / 64), 128>>>(query, key, Wq, Wk);
    score_kernel<<<dim3(KK / KC, QQ / TQ, BB), 256>>>(valid_len, v_w);
    softout_kernel<<<dim3(QQ / TQO, BB, DD / 128), 128>>>(value, valid_len, out);
}